// round 4
// baseline (speedup 1.0000x reference)
#include <cuda_runtime.h>
#include <math.h>

// S=4 K=50 T=30 R=300 V=10000 HT=800 EH=200 BSZ=256 SK=200
#define SS 4
#define KK_ 50
#define TT 30
#define RR 300
#define VV 10000
#define HT_ 800
#define EH_ 200
#define BSZ_ 256
#define SK_ 200

#define LOGD  (-5.2983174f)
#define INV1  (1.0f/1.000001f)
#define INVD  (1.0f/0.005001f)
#define MAXLS 10.0f
#define MINLS (-10.0f)

// ---------------- device scratch (static; no runtime allocation) ----------------
__device__ float g_logit[6000u * 10000u];   // logits -> beta in place
__device__ float g_rhoT[300 * 10000];
__device__ float g_inp[BSZ_ * 10200];
__device__ float g_h1[BSZ_ * HT_];
__device__ float g_h2[BSZ_ * HT_];
__device__ float g_x[TT * EH_];
__device__ float g_xg[TT * 4 * EH_];
__device__ float g_outs[TT * EH_];
__device__ float g_Amu[TT * SK_];
__device__ float g_Als[TT * SK_];
__device__ float g_etas[TT * SK_];
__device__ float g_eta_td[BSZ_ * SK_];
__device__ float g_mu_sel[BSZ_ * KK_];
__device__ float g_ls_sel[BSZ_ * KK_];
__device__ float g_eta_sel[BSZ_ * KK_];
__device__ float g_theta[BSZ_ * KK_];
__device__ float g_src_mask[SS];
__device__ int   g_th_flag;
__device__ double g_acc_d[4];   // 0: -sum(bow*log), 1: kl_alpha, 2: kl_eta, 3: kl_theta raw

__device__ __forceinline__ float sigmf(float x) { return 1.0f / (1.0f + expf(-x)); }

// ---------------- init / zero ----------------
__global__ void init_kernel() {
    int i = threadIdx.x;
    if (i < 4)  g_acc_d[i] = 0.0;
    if (i == 0) g_th_flag = 0;
}

__global__ void zero_all() {
    int i = blockIdx.x * blockDim.x + threadIdx.x;
    if (i < TT * EH_)     g_x[i]  = 0.f;
    if (i < TT * 4 * EH_) g_xg[i] = 0.f;
    if (i < TT * SK_)     { g_Amu[i] = 0.f; g_Als[i] = 0.f; }
    if (i < BSZ_ * HT_)   { g_h1[i] = 0.f; g_h2[i] = 0.f; }
}

// ---------------- kl_alpha ----------------
__global__ void __launch_bounds__(256) kl_alpha_kernel(const float* __restrict__ mu,
                                                       const float* __restrict__ ls) {
    const int total = SS * KK_ * TT * RR;
    double local = 0.0;
    for (int o = blockIdx.x * blockDim.x + threadIdx.x; o < total; o += gridDim.x * blockDim.x) {
        float m = mu[o], l = ls[o];
        int t = (o / RR) % TT;
        float term;
        if (t == 0) {
            term = (expf(l) + m * m) * INV1 - 1.0f - l;
        } else {
            float pm = mu[o - RR];
            float d = m - pm;
            term = (expf(l) + d * d) * INVD - 1.0f + LOGD - l;
        }
        local += (double)term;
    }
    __shared__ double sred[256];
    int tid = threadIdx.x;
    sred[tid] = local; __syncthreads();
    for (int s = 128; s > 0; s >>= 1) { if (tid < s) sred[tid] += sred[tid + s]; __syncthreads(); }
    if (tid == 0) atomicAdd(&g_acc_d[1], 0.5 * sred[0]);
}

// ---------------- transpose rho (V,R) -> rhoT (R,V) ----------------
__global__ void transpose_rho(const float* __restrict__ rho) {
    __shared__ float t[32][33];
    int r0 = blockIdx.x * 32, v0 = blockIdx.y * 32;
    int tx = threadIdx.x, ty = threadIdx.y;
    #pragma unroll
    for (int i = 0; i < 4; i++) {
        int v = v0 + ty + i * 8, r = r0 + tx;
        t[ty + i * 8][tx] = (v < VV && r < RR) ? rho[(long)v * RR + r] : 0.f;
    }
    __syncthreads();
    #pragma unroll
    for (int i = 0; i < 4; i++) {
        int r = r0 + ty + i * 8, v = v0 + tx;
        if (r < RR && v < VV) g_rhoT[(long)r * VV + v] = t[tx][ty + i * 8];
    }
}

// ---------------- fp32 GEMM 128x128x8, optional split-K + atomic accumulate ----------------
__global__ void __launch_bounds__(256) sgemm128(const float* __restrict__ A, const float* __restrict__ B,
                                                float* __restrict__ C, int M, int N, int K,
                                                int lda, int ldb, int ldc, int kPerSplit, int accumulate) {
    __shared__ float As[8][128];
    __shared__ float Bs[8][132];
    int m0 = blockIdx.x * 128, n0 = blockIdx.y * 128;
    int k0 = blockIdx.z * kPerSplit;
    int k1 = min(K, k0 + kPerSplit);
    int tid = threadIdx.x;
    int tx = tid & 15, ty = tid >> 4;
    float acc[8][8];
    #pragma unroll
    for (int i = 0; i < 8; i++)
        #pragma unroll
        for (int j = 0; j < 8; j++) acc[i][j] = 0.f;

    for (int kt = k0; kt < k1; kt += 8) {
        #pragma unroll
        for (int i = 0; i < 4; i++) {
            int e = tid + 256 * i;
            int r = e >> 3, cc = e & 7;
            int gm = m0 + r, gk = kt + cc;
            As[cc][r] = (gm < M && gk < k1) ? A[(long)gm * lda + gk] : 0.f;
        }
        #pragma unroll
        for (int i = 0; i < 4; i++) {
            int e = tid + 256 * i;
            int kk2 = e >> 7, nn = e & 127;
            int gk = kt + kk2, gn = n0 + nn;
            Bs[kk2][nn] = (gk < k1 && gn < N) ? B[(long)gk * ldb + gn] : 0.f;
        }
        __syncthreads();
        #pragma unroll
        for (int kk2 = 0; kk2 < 8; kk2++) {
            float a[8], b[8];
            #pragma unroll
            for (int i = 0; i < 8; i++) a[i] = As[kk2][ty * 8 + i];
            #pragma unroll
            for (int j = 0; j < 8; j++) b[j] = Bs[kk2][tx * 8 + j];
            #pragma unroll
            for (int i = 0; i < 8; i++)
                #pragma unroll
                for (int j = 0; j < 8; j++) acc[i][j] += a[i] * b[j];
        }
        __syncthreads();
    }
    #pragma unroll
    for (int i = 0; i < 8; i++) {
        int gm = m0 + ty * 8 + i;
        if (gm >= M) continue;
        #pragma unroll
        for (int j = 0; j < 8; j++) {
            int gn = n0 + tx * 8 + j;
            if (gn >= N) continue;
            if (accumulate) atomicAdd(&C[(long)gm * ldc + gn], acc[i][j]);
            else            C[(long)gm * ldc + gn] = acc[i][j];
        }
    }
}

// ---------------- skinny GEMM (M<=32): C += A(MxK)@B(KxN) ----------------
__global__ void __launch_bounds__(256) skinny_gemm(const float* __restrict__ A, const float* __restrict__ B,
                                                   float* __restrict__ C, int M, int N, int K,
                                                   int lda, int ldb, int ldc, int kPerSplit) {
    int n = blockIdx.x * 64 + (threadIdx.x & 63);
    int r0 = threadIdx.x >> 6;
    int k0 = blockIdx.y * kPerSplit;
    int k1 = min(K, k0 + kPerSplit);
    if (n >= N) return;
    float acc[8];
    #pragma unroll
    for (int mi = 0; mi < 8; mi++) acc[mi] = 0.f;
    for (int k = k0; k < k1; k++) {
        float bb = B[(long)k * ldb + n];
        #pragma unroll
        for (int mi = 0; mi < 8; mi++) {
            int m = r0 + mi * 4;
            if (m < M) acc[mi] += A[(long)m * lda + k] * bb;
        }
    }
    #pragma unroll
    for (int mi = 0; mi < 8; mi++) {
        int m = r0 + mi * 4;
        if (m < M) atomicAdd(&C[(long)m * ldc + n], acc[mi]);
    }
}

// ---------------- bias (+optional 2nd bias, optional relu) in place ----------------
__global__ void addbias(float* __restrict__ C, const float* __restrict__ b1,
                        const float* __restrict__ b2, int rows, int cols, int relu) {
    int i = blockIdx.x * blockDim.x + threadIdx.x;
    if (i >= rows * cols) return;
    int c = i % cols;
    float v = C[i] + b1[c] + (b2 ? b2[c] : 0.f);
    if (relu) v = fmaxf(v, 0.f);
    C[i] = v;
}

// ---------------- softmax over rows of VV, in place ----------------
__global__ void __launch_bounds__(256) softmax_kernel(float* __restrict__ P) {
    __shared__ float buf[VV];
    __shared__ float red[256];
    long base = (long)blockIdx.x * VV;
    int tid = threadIdx.x;
    float m = -1e30f;
    for (int v = tid; v < VV; v += 256) { float x = P[base + v]; buf[v] = x; m = fmaxf(m, x); }
    red[tid] = m; __syncthreads();
    for (int s = 128; s > 0; s >>= 1) { if (tid < s) red[tid] = fmaxf(red[tid], red[tid + s]); __syncthreads(); }
    m = red[0]; __syncthreads();
    float sum = 0.f;
    for (int v = tid; v < VV; v += 256) { float e = expf(buf[v] - m); buf[v] = e; sum += e; }
    red[tid] = sum; __syncthreads();
    for (int s = 128; s > 0; s >>= 1) { if (tid < s) red[tid] += red[tid + s]; __syncthreads(); }
    float inv = 1.0f / red[0];
    for (int v = tid; v < VV; v += 256) P[base + v] = buf[v] * inv;
}

// ---------------- LSTM: single block, 800 threads (no cross-block sync) ----------------
__global__ void __launch_bounds__(800) lstm_kernel(const float* __restrict__ Whh) {
    __shared__ float hsh[EH_];
    __shared__ float csh[EH_];
    __shared__ float gs[4 * EH_];
    int tid = threadIdx.x;
    if (tid < EH_) { hsh[tid] = 0.f; csh[tid] = 0.f; }
    __syncthreads();
    for (int t = 0; t < TT; t++) {
        float acc = g_xg[t * 800 + tid];
        #pragma unroll 8
        for (int i = 0; i < EH_; i++) acc += hsh[i] * Whh[i * 800 + tid];
        gs[tid] = acc;
        __syncthreads();
        if (tid < EH_) {
            float c = sigmf(gs[200 + tid]) * csh[tid] + sigmf(gs[tid]) * tanhf(gs[400 + tid]);
            csh[tid] = c;
            float h = sigmf(gs[600 + tid]) * tanhf(c);
            hsh[tid] = h;
            g_outs[t * EH_ + tid] = h;
        }
        __syncthreads();
    }
}

// ---------------- eta chain: single block, 512 threads ----------------
__global__ void __launch_bounds__(512) eta_kernel(const float* __restrict__ Wmu, const float* __restrict__ Wls,
                                                  const float* __restrict__ bmu, const float* __restrict__ bls) {
    __shared__ float eprev[SK_];
    __shared__ float mu_s[SK_];
    __shared__ float ls_s[SK_];
    __shared__ int flag;
    __shared__ double sredd[512];
    int tid = threadIdx.x;
    double kl = 0.0;
    for (int t = 0; t < TT; t++) {
        if (tid == 0) flag = 0;
        __syncthreads();
        bool isMu = (tid < SK_);
        bool isLs = (tid >= 256 && tid < 256 + SK_);
        if (isMu || isLs) {
            int j = isMu ? tid : tid - 256;
            float acc = isMu ? (g_Amu[t * SK_ + j] + bmu[j]) : (g_Als[t * SK_ + j] + bls[j]);
            if (t > 0) {
                const float* W = isMu ? Wmu : Wls;
                #pragma unroll 8
                for (int i = 0; i < SK_; i++) acc += eprev[i] * W[(200 + i) * SK_ + j];
            }
            if (isMu) { mu_s[j] = acc; g_etas[t * SK_ + j] = acc; }
            else {
                ls_s[j] = acc;
                if (t > 0 && acc > MAXLS) atomicOr(&flag, 1);
            }
        }
        __syncthreads();
        if (tid < SK_) {
            float muv = mu_s[tid];
            float lsv = ls_s[tid];
            if (t == 0) {
                kl += 0.5 * (double)((expf(lsv) + muv * muv) * INV1 - 1.0f - lsv);
            } else {
                lsv = flag ? fminf(lsv, MAXLS) : fmaxf(lsv, MINLS);
                float d = muv - eprev[tid];
                kl += 0.5 * (double)((expf(lsv) + d * d) * INVD - 1.0f + LOGD - lsv);
            }
        }
        __syncthreads();
        if (tid < SK_) eprev[tid] = mu_s[tid];
        __syncthreads();
    }
    sredd[tid] = kl;
    __syncthreads();
    for (int s = 256; s > 0; s >>= 1) { if (tid < s) sredd[tid] += sredd[tid + s]; __syncthreads(); }
    if (tid == 0) atomicAdd(&g_acc_d[2], sredd[0]);
}

// ---------------- source mask ----------------
__global__ void srcmask_kernel(const int* __restrict__ sources) {
    int tid = threadIdx.x;
    if (tid < SS) g_src_mask[tid] = 0.f;
    __syncthreads();
    if (tid < BSZ_) g_src_mask[sources[tid]] = 1.0f;
}

// ---------------- build inp = [nbows | eta_td] ----------------
__global__ void __launch_bounds__(256) eta_td_kernel(const float* __restrict__ nbows,
                                                     const int* __restrict__ times) {
    int b = blockIdx.x, tid = threadIdx.x;
    const float4* src = (const float4*)(nbows + (long)b * VV);
    float4* dst = (float4*)(g_inp + (long)b * 10200);
    for (int i = tid; i < VV / 4; i += 256) dst[i] = src[i];
    int t = times[b];
    if (tid < SK_) {
        float v = g_etas[t * SK_ + tid] * g_src_mask[tid / KK_];
        g_inp[(long)b * 10200 + VV + tid] = v;
        g_eta_td[b * SK_ + tid] = v;
    }
}

// ---------------- theta select ----------------
__global__ void __launch_bounds__(256) theta_sel_kernel(const int* __restrict__ sources,
        const float* __restrict__ Wmu, const float* __restrict__ bmu,
        const float* __restrict__ Wls, const float* __restrict__ bls) {
    __shared__ float hsh[HT_];
    int b = blockIdx.x, tid = threadIdx.x;
    for (int i = tid; i < HT_; i += 256) hsh[i] = g_h2[(long)b * HT_ + i];
    __syncthreads();
    int s = sources[b];
    if (tid < 50) {
        int col = s * 50 + tid;
        float acc = bmu[col];
        #pragma unroll 4
        for (int i = 0; i < HT_; i++) acc += hsh[i] * Wmu[i * SK_ + col];
        g_mu_sel[b * 50 + tid] = acc;
        g_eta_sel[b * 50 + tid] = g_eta_td[b * SK_ + col];
    } else if (tid >= 64 && tid < 114) {
        int k = tid - 64, col = s * 50 + k;
        float acc = bls[col];
        #pragma unroll 4
        for (int i = 0; i < HT_; i++) acc += hsh[i] * Wls[i * SK_ + col];
        g_ls_sel[b * 50 + k] = acc;
        if (acc > MAXLS) atomicOr(&g_th_flag, 1);
    }
}

// ---------------- theta softmax + kl_theta ----------------
__global__ void __launch_bounds__(64) theta_fin_kernel() {
    int b = blockIdx.x, tid = threadIdx.x;
    __shared__ float sm[64];
    __shared__ double sd[64];
    bool act = tid < 50;
    float muv = 0.f, lsv = 0.f, esv = 0.f;
    if (act) {
        muv = g_mu_sel[b * 50 + tid];
        lsv = g_ls_sel[b * 50 + tid];
        lsv = g_th_flag ? fminf(lsv, MAXLS) : fmaxf(lsv, MINLS);
        esv = g_eta_sel[b * 50 + tid];
    }
    sm[tid] = act ? muv : -1e30f; __syncthreads();
    for (int s = 32; s > 0; s >>= 1) { if (tid < s) sm[tid] = fmaxf(sm[tid], sm[tid + s]); __syncthreads(); }
    float mx = sm[0]; __syncthreads();
    float ex = act ? expf(muv - mx) : 0.f;
    sm[tid] = ex; __syncthreads();
    for (int s = 32; s > 0; s >>= 1) { if (tid < s) sm[tid] += sm[tid + s]; __syncthreads(); }
    float inv = 1.0f / sm[0];
    if (act) g_theta[b * 50 + tid] = ex * inv;
    double term = 0.0;
    if (act) {
        float d = muv - esv;
        term = (double)((expf(lsv) + d * d) * INV1 - 1.0f - lsv);
    }
    sd[tid] = term; __syncthreads();
    for (int s = 32; s > 0; s >>= 1) { if (tid < s) sd[tid] += sd[tid + s]; __syncthreads(); }
    if (tid == 0) atomicAdd(&g_acc_d[3], 0.5 * sd[0]);
}

// ---------------- nll ----------------
__global__ void __launch_bounds__(256) nll_kernel(const float* __restrict__ beta,
                                                  const float* __restrict__ bows,
                                                  const int* __restrict__ times,
                                                  const int* __restrict__ sources) {
    __shared__ float th[50];
    __shared__ const float* rp[50];
    __shared__ double sred[256];
    int b = blockIdx.x, tid = threadIdx.x;
    int s = sources[b], t = times[b];
    if (tid < 50) {
        th[tid] = g_theta[b * 50 + tid];
        rp[tid] = beta + (long)(s * 1500 + tid * 30 + t) * VV;
    }
    __syncthreads();
    const float* br = bows + (long)b * VV;
    double local = 0.0;
    for (int v = tid; v < VV; v += 256) {
        float a0 = 0.f, a1 = 0.f;
        #pragma unroll
        for (int k = 0; k < 50; k += 2) {
            a0 += th[k] * rp[k][v];
            a1 += th[k + 1] * rp[k + 1][v];
        }
        local += (double)(br[v] * logf(a0 + a1));
    }
    sred[tid] = local; __syncthreads();
    for (int s2 = 128; s2 > 0; s2 >>= 1) { if (tid < s2) sred[tid] += sred[tid + s2]; __syncthreads(); }
    if (tid == 0) atomicAdd(&g_acc_d[0], -sred[0]);
}

// ---------------- finalize ----------------
__global__ void finalize_kernel(const void* __restrict__ ndp, float* __restrict__ out) {
    if (threadIdx.x == 0) {
        int iv = *(const int*)ndp;
        float nd = (iv > 0 && iv < 1073741824) ? (float)iv : *(const float*)ndp;
        float coeff = nd / (float)BSZ_;
        out[0] = (float)g_acc_d[0] * coeff;
        out[1] = (float)g_acc_d[1];
        out[2] = (float)g_acc_d[2];
        out[3] = (float)g_acc_d[3] * coeff;
    }
}

// ---------------- host launcher ----------------
extern "C" void kernel_launch(void* const* d_in, const int* in_sizes, int n_in,
                              void* d_out, int out_size) {
    const float* bows    = (const float*)d_in[1];
    const float* nbows   = (const float*)d_in[2];
    const int*   times   = (const int*)d_in[3];
    const int*   sources = (const int*)d_in[4];
    const float* rnn_inp = (const float*)d_in[5];
    const void*  numdocs = d_in[6];
    const float* rho     = (const float*)d_in[7];
    const float* mu_q    = (const float*)d_in[8];
    const float* ls_q    = (const float*)d_in[9];
    const float* W_qt1   = (const float*)d_in[10];
    const float* b_qt1   = (const float*)d_in[11];
    const float* W_qt2   = (const float*)d_in[12];
    const float* b_qt2   = (const float*)d_in[13];
    const float* W_mu_th = (const float*)d_in[14];
    const float* b_mu_th = (const float*)d_in[15];
    const float* W_ls_th = (const float*)d_in[16];
    const float* b_ls_th = (const float*)d_in[17];
    const float* W_map   = (const float*)d_in[18];
    const float* b_map   = (const float*)d_in[19];
    const float* W_ih    = (const float*)d_in[20];
    const float* W_hh    = (const float*)d_in[21];
    const float* b_ih    = (const float*)d_in[22];
    const float* b_hh    = (const float*)d_in[23];
    const float* W_mu_e  = (const float*)d_in[24];
    const float* b_mu_e  = (const float*)d_in[25];
    const float* W_ls_e  = (const float*)d_in[26];
    const float* b_ls_e  = (const float*)d_in[27];

    float *p_logit, *p_inp, *p_h1, *p_h2, *p_rhoT, *p_x, *p_xg, *p_outs, *p_Amu, *p_Als;
    cudaGetSymbolAddress((void**)&p_logit, g_logit);
    cudaGetSymbolAddress((void**)&p_inp,   g_inp);
    cudaGetSymbolAddress((void**)&p_h1,    g_h1);
    cudaGetSymbolAddress((void**)&p_h2,    g_h2);
    cudaGetSymbolAddress((void**)&p_rhoT,  g_rhoT);
    cudaGetSymbolAddress((void**)&p_x,     g_x);
    cudaGetSymbolAddress((void**)&p_xg,    g_xg);
    cudaGetSymbolAddress((void**)&p_outs,  g_outs);
    cudaGetSymbolAddress((void**)&p_Amu,   g_Amu);
    cudaGetSymbolAddress((void**)&p_Als,   g_Als);

    init_kernel<<<1, 32>>>();
    zero_all<<<800, 256>>>();
    kl_alpha_kernel<<<256, 256>>>(mu_q, ls_q);

    // beta = softmax(alphas @ rhoT)
    transpose_rho<<<dim3(10, 313), dim3(32, 8)>>>(rho);
    sgemm128<<<dim3(47, 79, 1), 256>>>(mu_q, p_rhoT, p_logit,
                                       6000, VV, RR, RR, VV, VV, RR, 0);
    softmax_kernel<<<6000, 256>>>(p_logit);

    // LSTM input: x = rnn_inp @ W_map + b_map ; xg = x @ W_ih + b_ih + b_hh
    skinny_gemm<<<dim3(4, 8), 256>>>(rnn_inp, W_map, p_x, TT, EH_, VV, VV, EH_, EH_, 1250);
    addbias<<<(TT * EH_ + 255) / 256, 256>>>(p_x, b_map, nullptr, TT, EH_, 0);
    skinny_gemm<<<dim3(13, 1), 256>>>(p_x, W_ih, p_xg, TT, 4 * EH_, EH_, EH_, 4 * EH_, 4 * EH_, EH_);
    addbias<<<(TT * 4 * EH_ + 255) / 256, 256>>>(p_xg, b_ih, b_hh, TT, 4 * EH_, 0);
    lstm_kernel<<<1, 800>>>(W_hh);

    // eta precompute: outs @ W_{mu,ls}_eta[0:200,:], then sequential chain
    skinny_gemm<<<dim3(4, 1), 256>>>(p_outs, W_mu_e, p_Amu, TT, SK_, EH_, EH_, SK_, SK_, EH_);
    skinny_gemm<<<dim3(4, 1), 256>>>(p_outs, W_ls_e, p_Als, TT, SK_, EH_, EH_, SK_, SK_, EH_);
    eta_kernel<<<1, 512>>>(W_mu_e, W_ls_e, b_mu_e, b_ls_e);

    // doc-side MLP
    srcmask_kernel<<<1, 256>>>(sources);
    eta_td_kernel<<<256, 256>>>(nbows, times);
    sgemm128<<<dim3(2, 7, 8), 256>>>(p_inp, W_qt1, p_h1,
                                     BSZ_, HT_, 10200, 10200, HT_, HT_, 1275, 1);
    addbias<<<(BSZ_ * HT_ + 255) / 256, 256>>>(p_h1, b_qt1, nullptr, BSZ_, HT_, 1);
    sgemm128<<<dim3(2, 7, 2), 256>>>(p_h1, W_qt2, p_h2,
                                     BSZ_, HT_, HT_, HT_, HT_, HT_, 400, 1);
    addbias<<<(BSZ_ * HT_ + 255) / 256, 256>>>(p_h2, b_qt2, nullptr, BSZ_, HT_, 1);

    theta_sel_kernel<<<256, 256>>>(sources, W_mu_th, b_mu_th, W_ls_th, b_ls_th);
    theta_fin_kernel<<<256, 64>>>();
    nll_kernel<<<256, 256>>>(p_logit, bows, times, sources);
    finalize_kernel<<<1, 32>>>(numdocs, (float*)d_out);
}

// round 5
// speedup vs baseline: 1.2117x; 1.2117x over previous
#include <cuda_runtime.h>
#include <math.h>
#include <stdint.h>

// S=4 K=50 T=30 R=300 V=10000 HT=800 EH=200 BSZ=256 SK=200
#define SS 4
#define KK_ 50
#define TT 30
#define RR 300
#define VV 10000
#define HT_ 800
#define EH_ 200
#define BSZ_ 256
#define SK_ 200

#define LOGD  (-5.2983174f)
#define INV1  (1.0f/1.000001f)
#define INVD  (1.0f/0.005001f)
#define MAXLS 10.0f
#define MINLS (-10.0f)

// ---------------- device scratch (static; no runtime allocation) ----------------
__device__ float g_logit[6000u * 10000u];   // logits -> beta in place
__device__ float g_inp[BSZ_ * 10200];
__device__ float g_h1[BSZ_ * HT_];
__device__ float g_h2[BSZ_ * HT_];
__device__ float g_x[TT * EH_];
__device__ float g_xg[TT * 4 * EH_];
__device__ float g_outs[TT * EH_];
__device__ float g_Amu[TT * SK_];
__device__ float g_Als[TT * SK_];
__device__ float g_etas[TT * SK_];
__device__ float g_eta_td[BSZ_ * SK_];
__device__ float g_mu_sel[BSZ_ * KK_];
__device__ float g_ls_sel[BSZ_ * KK_];
__device__ float g_eta_sel[BSZ_ * KK_];
__device__ float g_theta[BSZ_ * KK_];
__device__ float g_src_mask[SS];
__device__ int   g_th_flag;
__device__ double g_acc_d[4];   // 0: -sum(bow*log), 1: kl_alpha, 2: kl_eta, 3: kl_theta raw

__device__ __forceinline__ float sigmf(float x) { return 1.0f / (1.0f + expf(-x)); }

__device__ __forceinline__ uint32_t f2tf32(float x) {
    uint32_t o;
    asm("cvt.rna.tf32.f32 %0, %1;" : "=r"(o) : "f"(x));
    return o;
}

// ---------------- init / zero ----------------
__global__ void init_kernel() {
    int i = threadIdx.x;
    if (i < 4)  g_acc_d[i] = 0.0;
    if (i == 0) g_th_flag = 0;
}

__global__ void zero_all() {
    int i = blockIdx.x * blockDim.x + threadIdx.x;
    if (i < TT * EH_)     g_x[i]  = 0.f;
    if (i < TT * 4 * EH_) g_xg[i] = 0.f;
    if (i < TT * SK_)     { g_Amu[i] = 0.f; g_Als[i] = 0.f; }
    if (i < BSZ_ * HT_)   { g_h1[i] = 0.f; g_h2[i] = 0.f; }
}

// ---------------- kl_alpha ----------------
__global__ void __launch_bounds__(256) kl_alpha_kernel(const float* __restrict__ mu,
                                                       const float* __restrict__ ls) {
    const int total = SS * KK_ * TT * RR;
    double local = 0.0;
    for (int o = blockIdx.x * blockDim.x + threadIdx.x; o < total; o += gridDim.x * blockDim.x) {
        float m = mu[o], l = ls[o];
        int t = (o / RR) % TT;
        float term;
        if (t == 0) {
            term = (expf(l) + m * m) * INV1 - 1.0f - l;
        } else {
            float pm = mu[o - RR];
            float d = m - pm;
            term = (expf(l) + d * d) * INVD - 1.0f + LOGD - l;
        }
        local += (double)term;
    }
    __shared__ double sred[256];
    int tid = threadIdx.x;
    sred[tid] = local; __syncthreads();
    for (int s = 128; s > 0; s >>= 1) { if (tid < s) sred[tid] += sred[tid + s]; __syncthreads(); }
    if (tid == 0) atomicAdd(&g_acc_d[1], 0.5 * sred[0]);
}

// ---------------- tf32 tensor-core GEMM: logit = A(6000x300) @ rho(10000x300)^T ----------------
// C[m][n] = sum_k A[m][k] * Brows[n][k]   (Brows = rho, native layout, no transpose)
// Block tile 128x128, kc=16 chunks, 8 warps each computing 64x32 via m16n8k8 tf32 mma.
#define GM 6000
#define GN 10000
#define GK 300

__global__ void __launch_bounds__(256) tf32_gemm(const float* __restrict__ A,
                                                 const float* __restrict__ Brows,
                                                 float* __restrict__ C) {
    __shared__ uint32_t As[128 * 20];   // [row m][k], pitch 20 (conflict-free for frag loads)
    __shared__ uint32_t Bs[128 * 20];   // [row n][k], pitch 20

    const int tid  = threadIdx.x;
    const int lane = tid & 31;
    const int wid  = tid >> 5;
    const int wm   = wid & 1;        // 2 warps along M
    const int wn   = wid >> 1;       // 4 warps along N
    const int g    = lane >> 2;      // groupID 0..7
    const int tg   = lane & 3;       // thread-in-group 0..3

    const int m0 = blockIdx.x * 128;
    const int n0 = blockIdx.y * 128;

    float c[4][4][4];
    #pragma unroll
    for (int mi = 0; mi < 4; mi++)
        #pragma unroll
        for (int ni = 0; ni < 4; ni++)
            #pragma unroll
            for (int r = 0; r < 4; r++) c[mi][ni][r] = 0.f;

    const int r  = tid >> 1;         // 0..127: row within tile
    const int qh = (tid & 1) * 2;    // first of two float4 quads this thread loads

    for (int chunk = 0; chunk < 19; chunk++) {
        const int k0 = chunk * 16;
        // ---- load A tile ----
        {
            const int gm = m0 + r;
            #pragma unroll
            for (int qq = 0; qq < 2; qq++) {
                const int q = qh + qq;
                const int kb = k0 + 4 * q;
                float4 v = make_float4(0.f, 0.f, 0.f, 0.f);
                if (gm < GM) {
                    if (kb + 3 < GK) {
                        v = *(const float4*)(A + (long)gm * GK + kb);
                    } else {
                        if (kb     < GK) v.x = A[(long)gm * GK + kb];
                        if (kb + 1 < GK) v.y = A[(long)gm * GK + kb + 1];
                        if (kb + 2 < GK) v.z = A[(long)gm * GK + kb + 2];
                        if (kb + 3 < GK) v.w = A[(long)gm * GK + kb + 3];
                    }
                }
                uint4 t;
                t.x = f2tf32(v.x); t.y = f2tf32(v.y); t.z = f2tf32(v.z); t.w = f2tf32(v.w);
                *(uint4*)&As[r * 20 + 4 * q] = t;
            }
        }
        // ---- load B tile (rho rows, native [n][k]) ----
        {
            const int gn = n0 + r;
            #pragma unroll
            for (int qq = 0; qq < 2; qq++) {
                const int q = qh + qq;
                const int kb = k0 + 4 * q;
                float4 v = make_float4(0.f, 0.f, 0.f, 0.f);
                if (gn < GN) {
                    if (kb + 3 < GK) {
                        v = *(const float4*)(Brows + (long)gn * GK + kb);
                    } else {
                        if (kb     < GK) v.x = Brows[(long)gn * GK + kb];
                        if (kb + 1 < GK) v.y = Brows[(long)gn * GK + kb + 1];
                        if (kb + 2 < GK) v.z = Brows[(long)gn * GK + kb + 2];
                        if (kb + 3 < GK) v.w = Brows[(long)gn * GK + kb + 3];
                    }
                }
                uint4 t;
                t.x = f2tf32(v.x); t.y = f2tf32(v.y); t.z = f2tf32(v.z); t.w = f2tf32(v.w);
                *(uint4*)&Bs[r * 20 + 4 * q] = t;
            }
        }
        __syncthreads();

        #pragma unroll
        for (int ks = 0; ks < 16; ks += 8) {
            uint32_t af[4][4];
            #pragma unroll
            for (int mi = 0; mi < 4; mi++) {
                const int mrow = wm * 64 + mi * 16 + g;
                af[mi][0] = As[(mrow)     * 20 + ks + tg];
                af[mi][1] = As[(mrow + 8) * 20 + ks + tg];
                af[mi][2] = As[(mrow)     * 20 + ks + tg + 4];
                af[mi][3] = As[(mrow + 8) * 20 + ks + tg + 4];
            }
            uint32_t bf[4][2];
            #pragma unroll
            for (int ni = 0; ni < 4; ni++) {
                const int nrow = wn * 32 + ni * 8 + g;
                bf[ni][0] = Bs[nrow * 20 + ks + tg];
                bf[ni][1] = Bs[nrow * 20 + ks + tg + 4];
            }
            #pragma unroll
            for (int mi = 0; mi < 4; mi++)
                #pragma unroll
                for (int ni = 0; ni < 4; ni++) {
                    asm volatile(
                        "mma.sync.aligned.m16n8k8.row.col.f32.tf32.tf32.f32 "
                        "{%0,%1,%2,%3}, {%4,%5,%6,%7}, {%8,%9}, {%0,%1,%2,%3};"
                        : "+f"(c[mi][ni][0]), "+f"(c[mi][ni][1]),
                          "+f"(c[mi][ni][2]), "+f"(c[mi][ni][3])
                        : "r"(af[mi][0]), "r"(af[mi][1]), "r"(af[mi][2]), "r"(af[mi][3]),
                          "r"(bf[ni][0]), "r"(bf[ni][1]));
                }
        }
        __syncthreads();
    }

    // ---- epilogue: c0,c1 -> (row, col..col+1); c2,c3 -> (row+8, ...) ----
    #pragma unroll
    for (int mi = 0; mi < 4; mi++) {
        const int row = m0 + wm * 64 + mi * 16 + g;
        #pragma unroll
        for (int ni = 0; ni < 4; ni++) {
            const int col = n0 + wn * 32 + ni * 8 + tg * 2;
            if (col < GN) {
                if (row < GM) {
                    float2 v0 = make_float2(c[mi][ni][0], c[mi][ni][1]);
                    *(float2*)&C[(long)row * GN + col] = v0;
                }
                if (row + 8 < GM) {
                    float2 v1 = make_float2(c[mi][ni][2], c[mi][ni][3]);
                    *(float2*)&C[(long)(row + 8) * GN + col] = v1;
                }
            }
        }
    }
}

// ---------------- fp32 GEMM 128x128x8, optional split-K + atomic accumulate ----------------
__global__ void __launch_bounds__(256) sgemm128(const float* __restrict__ A, const float* __restrict__ B,
                                                float* __restrict__ C, int M, int N, int K,
                                                int lda, int ldb, int ldc, int kPerSplit, int accumulate) {
    __shared__ float As[8][128];
    __shared__ float Bs[8][132];
    int m0 = blockIdx.x * 128, n0 = blockIdx.y * 128;
    int k0 = blockIdx.z * kPerSplit;
    int k1 = min(K, k0 + kPerSplit);
    int tid = threadIdx.x;
    int tx = tid & 15, ty = tid >> 4;
    float acc[8][8];
    #pragma unroll
    for (int i = 0; i < 8; i++)
        #pragma unroll
        for (int j = 0; j < 8; j++) acc[i][j] = 0.f;

    for (int kt = k0; kt < k1; kt += 8) {
        #pragma unroll
        for (int i = 0; i < 4; i++) {
            int e = tid + 256 * i;
            int r = e >> 3, cc = e & 7;
            int gm = m0 + r, gk = kt + cc;
            As[cc][r] = (gm < M && gk < k1) ? A[(long)gm * lda + gk] : 0.f;
        }
        #pragma unroll
        for (int i = 0; i < 4; i++) {
            int e = tid + 256 * i;
            int kk2 = e >> 7, nn = e & 127;
            int gk = kt + kk2, gn = n0 + nn;
            Bs[kk2][nn] = (gk < k1 && gn < N) ? B[(long)gk * ldb + gn] : 0.f;
        }
        __syncthreads();
        #pragma unroll
        for (int kk2 = 0; kk2 < 8; kk2++) {
            float a[8], b[8];
            #pragma unroll
            for (int i = 0; i < 8; i++) a[i] = As[kk2][ty * 8 + i];
            #pragma unroll
            for (int j = 0; j < 8; j++) b[j] = Bs[kk2][tx * 8 + j];
            #pragma unroll
            for (int i = 0; i < 8; i++)
                #pragma unroll
                for (int j = 0; j < 8; j++) acc[i][j] += a[i] * b[j];
        }
        __syncthreads();
    }
    #pragma unroll
    for (int i = 0; i < 8; i++) {
        int gm = m0 + ty * 8 + i;
        if (gm >= M) continue;
        #pragma unroll
        for (int j = 0; j < 8; j++) {
            int gn = n0 + tx * 8 + j;
            if (gn >= N) continue;
            if (accumulate) atomicAdd(&C[(long)gm * ldc + gn], acc[i][j]);
            else            C[(long)gm * ldc + gn] = acc[i][j];
        }
    }
}

// ---------------- skinny GEMM (M<=32): C += A(MxK)@B(KxN) ----------------
__global__ void __launch_bounds__(256) skinny_gemm(const float* __restrict__ A, const float* __restrict__ B,
                                                   float* __restrict__ C, int M, int N, int K,
                                                   int lda, int ldb, int ldc, int kPerSplit) {
    int n = blockIdx.x * 64 + (threadIdx.x & 63);
    int r0 = threadIdx.x >> 6;
    int k0 = blockIdx.y * kPerSplit;
    int k1 = min(K, k0 + kPerSplit);
    if (n >= N) return;
    float acc[8];
    #pragma unroll
    for (int mi = 0; mi < 8; mi++) acc[mi] = 0.f;
    for (int k = k0; k < k1; k++) {
        float bb = B[(long)k * ldb + n];
        #pragma unroll
        for (int mi = 0; mi < 8; mi++) {
            int m = r0 + mi * 4;
            if (m < M) acc[mi] += A[(long)m * lda + k] * bb;
        }
    }
    #pragma unroll
    for (int mi = 0; mi < 8; mi++) {
        int m = r0 + mi * 4;
        if (m < M) atomicAdd(&C[(long)m * ldc + n], acc[mi]);
    }
}

// ---------------- bias (+optional 2nd bias, optional relu) in place ----------------
__global__ void addbias(float* __restrict__ C, const float* __restrict__ b1,
                        const float* __restrict__ b2, int rows, int cols, int relu) {
    int i = blockIdx.x * blockDim.x + threadIdx.x;
    if (i >= rows * cols) return;
    int c = i % cols;
    float v = C[i] + b1[c] + (b2 ? b2[c] : 0.f);
    if (relu) v = fmaxf(v, 0.f);
    C[i] = v;
}

// ---------------- softmax over rows of VV, in place ----------------
__global__ void __launch_bounds__(256) softmax_kernel(float* __restrict__ P) {
    __shared__ float buf[VV];
    __shared__ float red[256];
    long base = (long)blockIdx.x * VV;
    int tid = threadIdx.x;
    float m = -1e30f;
    for (int v = tid; v < VV; v += 256) { float x = P[base + v]; buf[v] = x; m = fmaxf(m, x); }
    red[tid] = m; __syncthreads();
    for (int s = 128; s > 0; s >>= 1) { if (tid < s) red[tid] = fmaxf(red[tid], red[tid + s]); __syncthreads(); }
    m = red[0]; __syncthreads();
    float sum = 0.f;
    for (int v = tid; v < VV; v += 256) { float e = expf(buf[v] - m); buf[v] = e; sum += e; }
    red[tid] = sum; __syncthreads();
    for (int s = 128; s > 0; s >>= 1) { if (tid < s) red[tid] += red[tid + s]; __syncthreads(); }
    float inv = 1.0f / red[0];
    for (int v = tid; v < VV; v += 256) P[base + v] = buf[v] * inv;
}

// ---------------- LSTM: single block, 800 threads ----------------
__global__ void __launch_bounds__(800) lstm_kernel(const float* __restrict__ Whh) {
    __shared__ float hsh[EH_];
    __shared__ float csh[EH_];
    __shared__ float gs[4 * EH_];
    int tid = threadIdx.x;
    if (tid < EH_) { hsh[tid] = 0.f; csh[tid] = 0.f; }
    __syncthreads();
    for (int t = 0; t < TT; t++) {
        float acc = g_xg[t * 800 + tid];
        #pragma unroll 8
        for (int i = 0; i < EH_; i++) acc += hsh[i] * Whh[i * 800 + tid];
        gs[tid] = acc;
        __syncthreads();
        if (tid < EH_) {
            float c = sigmf(gs[200 + tid]) * csh[tid] + sigmf(gs[tid]) * tanhf(gs[400 + tid]);
            csh[tid] = c;
            float h = sigmf(gs[600 + tid]) * tanhf(c);
            hsh[tid] = h;
            g_outs[t * EH_ + tid] = h;
        }
        __syncthreads();
    }
}

// ---------------- eta chain: single block, 512 threads ----------------
__global__ void __launch_bounds__(512) eta_kernel(const float* __restrict__ Wmu, const float* __restrict__ Wls,
                                                  const float* __restrict__ bmu, const float* __restrict__ bls) {
    __shared__ float eprev[SK_];
    __shared__ float mu_s[SK_];
    __shared__ float ls_s[SK_];
    __shared__ int flag;
    __shared__ double sredd[512];
    int tid = threadIdx.x;
    double kl = 0.0;
    for (int t = 0; t < TT; t++) {
        if (tid == 0) flag = 0;
        __syncthreads();
        bool isMu = (tid < SK_);
        bool isLs = (tid >= 256 && tid < 256 + SK_);
        if (isMu || isLs) {
            int j = isMu ? tid : tid - 256;
            float acc = isMu ? (g_Amu[t * SK_ + j] + bmu[j]) : (g_Als[t * SK_ + j] + bls[j]);
            if (t > 0) {
                const float* W = isMu ? Wmu : Wls;
                #pragma unroll 8
                for (int i = 0; i < SK_; i++) acc += eprev[i] * W[(200 + i) * SK_ + j];
            }
            if (isMu) { mu_s[j] = acc; g_etas[t * SK_ + j] = acc; }
            else {
                ls_s[j] = acc;
                if (t > 0 && acc > MAXLS) atomicOr(&flag, 1);
            }
        }
        __syncthreads();
        if (tid < SK_) {
            float muv = mu_s[tid];
            float lsv = ls_s[tid];
            if (t == 0) {
                kl += 0.5 * (double)((expf(lsv) + muv * muv) * INV1 - 1.0f - lsv);
            } else {
                lsv = flag ? fminf(lsv, MAXLS) : fmaxf(lsv, MINLS);
                float d = muv - eprev[tid];
                kl += 0.5 * (double)((expf(lsv) + d * d) * INVD - 1.0f + LOGD - lsv);
            }
        }
        __syncthreads();
        if (tid < SK_) eprev[tid] = mu_s[tid];
        __syncthreads();
    }
    sredd[tid] = kl;
    __syncthreads();
    for (int s = 256; s > 0; s >>= 1) { if (tid < s) sredd[tid] += sredd[tid + s]; __syncthreads(); }
    if (tid == 0) atomicAdd(&g_acc_d[2], sredd[0]);
}

// ---------------- source mask ----------------
__global__ void srcmask_kernel(const int* __restrict__ sources) {
    int tid = threadIdx.x;
    if (tid < SS) g_src_mask[tid] = 0.f;
    __syncthreads();
    if (tid < BSZ_) g_src_mask[sources[tid]] = 1.0f;
}

// ---------------- build inp = [nbows | eta_td] ----------------
__global__ void __launch_bounds__(256) eta_td_kernel(const float* __restrict__ nbows,
                                                     const int* __restrict__ times) {
    int b = blockIdx.x, tid = threadIdx.x;
    const float4* src = (const float4*)(nbows + (long)b * VV);
    float4* dst = (float4*)(g_inp + (long)b * 10200);
    for (int i = tid; i < VV / 4; i += 256) dst[i] = src[i];
    int t = times[b];
    if (tid < SK_) {
        float v = g_etas[t * SK_ + tid] * g_src_mask[tid / KK_];
        g_inp[(long)b * 10200 + VV + tid] = v;
        g_eta_td[b * SK_ + tid] = v;
    }
}

// ---------------- theta select ----------------
__global__ void __launch_bounds__(256) theta_sel_kernel(const int* __restrict__ sources,
        const float* __restrict__ Wmu, const float* __restrict__ bmu,
        const float* __restrict__ Wls, const float* __restrict__ bls) {
    __shared__ float hsh[HT_];
    int b = blockIdx.x, tid = threadIdx.x;
    for (int i = tid; i < HT_; i += 256) hsh[i] = g_h2[(long)b * HT_ + i];
    __syncthreads();
    int s = sources[b];
    if (tid < 50) {
        int col = s * 50 + tid;
        float acc = bmu[col];
        #pragma unroll 4
        for (int i = 0; i < HT_; i++) acc += hsh[i] * Wmu[i * SK_ + col];
        g_mu_sel[b * 50 + tid] = acc;
        g_eta_sel[b * 50 + tid] = g_eta_td[b * SK_ + col];
    } else if (tid >= 64 && tid < 114) {
        int k = tid - 64, col = s * 50 + k;
        float acc = bls[col];
        #pragma unroll 4
        for (int i = 0; i < HT_; i++) acc += hsh[i] * Wls[i * SK_ + col];
        g_ls_sel[b * 50 + k] = acc;
        if (acc > MAXLS) atomicOr(&g_th_flag, 1);
    }
}

// ---------------- theta softmax + kl_theta ----------------
__global__ void __launch_bounds__(64) theta_fin_kernel() {
    int b = blockIdx.x, tid = threadIdx.x;
    __shared__ float sm[64];
    __shared__ double sd[64];
    bool act = tid < 50;
    float muv = 0.f, lsv = 0.f, esv = 0.f;
    if (act) {
        muv = g_mu_sel[b * 50 + tid];
        lsv = g_ls_sel[b * 50 + tid];
        lsv = g_th_flag ? fminf(lsv, MAXLS) : fmaxf(lsv, MINLS);
        esv = g_eta_sel[b * 50 + tid];
    }
    sm[tid] = act ? muv : -1e30f; __syncthreads();
    for (int s = 32; s > 0; s >>= 1) { if (tid < s) sm[tid] = fmaxf(sm[tid], sm[tid + s]); __syncthreads(); }
    float mx = sm[0]; __syncthreads();
    float ex = act ? expf(muv - mx) : 0.f;
    sm[tid] = ex; __syncthreads();
    for (int s = 32; s > 0; s >>= 1) { if (tid < s) sm[tid] += sm[tid + s]; __syncthreads(); }
    float inv = 1.0f / sm[0];
    if (act) g_theta[b * 50 + tid] = ex * inv;
    double term = 0.0;
    if (act) {
        float d = muv - esv;
        term = (double)((expf(lsv) + d * d) * INV1 - 1.0f - lsv);
    }
    sd[tid] = term; __syncthreads();
    for (int s = 32; s > 0; s >>= 1) { if (tid < s) sd[tid] += sd[tid + s]; __syncthreads(); }
    if (tid == 0) atomicAdd(&g_acc_d[3], 0.5 * sd[0]);
}

// ---------------- nll ----------------
__global__ void __launch_bounds__(256) nll_kernel(const float* __restrict__ beta,
                                                  const float* __restrict__ bows,
                                                  const int* __restrict__ times,
                                                  const int* __restrict__ sources) {
    __shared__ float th[50];
    __shared__ const float* rp[50];
    __shared__ double sred[256];
    int b = blockIdx.x, tid = threadIdx.x;
    int s = sources[b], t = times[b];
    if (tid < 50) {
        th[tid] = g_theta[b * 50 + tid];
        rp[tid] = beta + (long)(s * 1500 + tid * 30 + t) * VV;
    }
    __syncthreads();
    const float* br = bows + (long)b * VV;
    double local = 0.0;
    for (int v = tid; v < VV; v += 256) {
        float a0 = 0.f, a1 = 0.f;
        #pragma unroll
        for (int k = 0; k < 50; k += 2) {
            a0 += th[k] * rp[k][v];
            a1 += th[k + 1] * rp[k + 1][v];
        }
        local += (double)(br[v] * logf(a0 + a1));
    }
    sred[tid] = local; __syncthreads();
    for (int s2 = 128; s2 > 0; s2 >>= 1) { if (tid < s2) sred[tid] += sred[tid + s2]; __syncthreads(); }
    if (tid == 0) atomicAdd(&g_acc_d[0], -sred[0]);
}

// ---------------- finalize ----------------
__global__ void finalize_kernel(const void* __restrict__ ndp, float* __restrict__ out) {
    if (threadIdx.x == 0) {
        int iv = *(const int*)ndp;
        float nd = (iv > 0 && iv < 1073741824) ? (float)iv : *(const float*)ndp;
        float coeff = nd / (float)BSZ_;
        out[0] = (float)g_acc_d[0] * coeff;
        out[1] = (float)g_acc_d[1];
        out[2] = (float)g_acc_d[2];
        out[3] = (float)g_acc_d[3] * coeff;
    }
}

// ---------------- host launcher ----------------
extern "C" void kernel_launch(void* const* d_in, const int* in_sizes, int n_in,
                              void* d_out, int out_size) {
    const float* bows    = (const float*)d_in[1];
    const float* nbows   = (const float*)d_in[2];
    const int*   times   = (const int*)d_in[3];
    const int*   sources = (const int*)d_in[4];
    const float* rnn_inp = (const float*)d_in[5];
    const void*  numdocs = d_in[6];
    const float* rho     = (const float*)d_in[7];
    const float* mu_q    = (const float*)d_in[8];
    const float* ls_q    = (const float*)d_in[9];
    const float* W_qt1   = (const float*)d_in[10];
    const float* b_qt1   = (const float*)d_in[11];
    const float* W_qt2   = (const float*)d_in[12];
    const float* b_qt2   = (const float*)d_in[13];
    const float* W_mu_th = (const float*)d_in[14];
    const float* b_mu_th = (const float*)d_in[15];
    const float* W_ls_th = (const float*)d_in[16];
    const float* b_ls_th = (const float*)d_in[17];
    const float* W_map   = (const float*)d_in[18];
    const float* b_map   = (const float*)d_in[19];
    const float* W_ih    = (const float*)d_in[20];
    const float* W_hh    = (const float*)d_in[21];
    const float* b_ih    = (const float*)d_in[22];
    const float* b_hh    = (const float*)d_in[23];
    const float* W_mu_e  = (const float*)d_in[24];
    const float* b_mu_e  = (const float*)d_in[25];
    const float* W_ls_e  = (const float*)d_in[26];
    const float* b_ls_e  = (const float*)d_in[27];

    float *p_logit, *p_inp, *p_h1, *p_h2, *p_x, *p_xg, *p_outs, *p_Amu, *p_Als;
    cudaGetSymbolAddress((void**)&p_logit, g_logit);
    cudaGetSymbolAddress((void**)&p_inp,   g_inp);
    cudaGetSymbolAddress((void**)&p_h1,    g_h1);
    cudaGetSymbolAddress((void**)&p_h2,    g_h2);
    cudaGetSymbolAddress((void**)&p_x,     g_x);
    cudaGetSymbolAddress((void**)&p_xg,    g_xg);
    cudaGetSymbolAddress((void**)&p_outs,  g_outs);
    cudaGetSymbolAddress((void**)&p_Amu,   g_Amu);
    cudaGetSymbolAddress((void**)&p_Als,   g_Als);

    init_kernel<<<1, 32>>>();
    zero_all<<<800, 256>>>();
    kl_alpha_kernel<<<256, 256>>>(mu_q, ls_q);

    // beta = softmax(alphas @ rho^T) — tensor-core tf32 GEMM, rho consumed natively
    tf32_gemm<<<dim3(47, 79), 256>>>(mu_q, rho, p_logit);
    softmax_kernel<<<6000, 256>>>(p_logit);

    // LSTM input: x = rnn_inp @ W_map + b_map ; xg = x @ W_ih + b_ih + b_hh
    skinny_gemm<<<dim3(4, 8), 256>>>(rnn_inp, W_map, p_x, TT, EH_, VV, VV, EH_, EH_, 1250);
    addbias<<<(TT * EH_ + 255) / 256, 256>>>(p_x, b_map, nullptr, TT, EH_, 0);
    skinny_gemm<<<dim3(13, 1), 256>>>(p_x, W_ih, p_xg, TT, 4 * EH_, EH_, EH_, 4 * EH_, 4 * EH_, EH_);
    addbias<<<(TT * 4 * EH_ + 255) / 256, 256>>>(p_xg, b_ih, b_hh, TT, 4 * EH_, 0);
    lstm_kernel<<<1, 800>>>(W_hh);

    // eta precompute + sequential chain
    skinny_gemm<<<dim3(4, 1), 256>>>(p_outs, W_mu_e, p_Amu, TT, SK_, EH_, EH_, SK_, SK_, EH_);
    skinny_gemm<<<dim3(4, 1), 256>>>(p_outs, W_ls_e, p_Als, TT, SK_, EH_, EH_, SK_, SK_, EH_);
    eta_kernel<<<1, 512>>>(W_mu_e, W_ls_e, b_mu_e, b_ls_e);

    // doc-side MLP
    srcmask_kernel<<<1, 256>>>(sources);
    eta_td_kernel<<<256, 256>>>(nbows, times);
    sgemm128<<<dim3(2, 7, 8), 256>>>(p_inp, W_qt1, p_h1,
                                     BSZ_, HT_, 10200, 10200, HT_, HT_, 1275, 1);
    addbias<<<(BSZ_ * HT_ + 255) / 256, 256>>>(p_h1, b_qt1, nullptr, BSZ_, HT_, 1);
    sgemm128<<<dim3(2, 7, 2), 256>>>(p_h1, W_qt2, p_h2,
                                     BSZ_, HT_, HT_, HT_, HT_, HT_, 400, 1);
    addbias<<<(BSZ_ * HT_ + 255) / 256, 256>>>(p_h2, b_qt2, nullptr, BSZ_, HT_, 1);

    theta_sel_kernel<<<256, 256>>>(sources, W_mu_th, b_mu_th, W_ls_th, b_ls_th);
    theta_fin_kernel<<<256, 64>>>();
    nll_kernel<<<256, 256>>>(p_logit, bows, times, sources);
    finalize_kernel<<<1, 32>>>(numdocs, (float*)d_out);
}